// round 5
// baseline (speedup 1.0000x reference)
#include <cuda_runtime.h>

// ---------------------------------------------------------------------------
// GCN plugin: 2x GCNConv (symmetric norm, self loops) + text-concat classifier
//   h1 = x @ W1;  agg1 = relu(CSR-aggregate(h1) + selfloop + b1)
//   h2 = agg1 @ W2; agg2 = CSR-aggregate(h2) + selfloop + b2
//   logits = agg2 @ Wc[:128] + (bc + text @ Wc[128:])   <- text term constant
// Aggregation is atomic-free: CSR built per launch, warp-per-node gather.
// edge_index is int32 (JAX downgrades int64 without x64 enabled).
// Inputs bound by element count (robust to metadata ordering).
// ---------------------------------------------------------------------------

#define NMAX   50000
#define INCH   256
#define HID    128
#define OUTC   1000
#define TEXTD  768
#define EMAX   800000

// Static scratch (allocation-free rule): ~109 MB total.
__device__ __align__(16) float g_h1[NMAX * HID];
__device__ __align__(16) float g_agg1[NMAX * HID];
__device__ __align__(16) float g_h2[NMAX * HID];
__device__ __align__(16) float g_agg2[NMAX * HID];
__device__ __align__(16) float g_disqrt[NMAX];
__device__ unsigned int        g_degcnt[NMAX];
__device__ int                 g_rowptr[NMAX + 1];
__device__ int                 g_fill[NMAX];
__device__ __align__(16) int   g_csrc[EMAX];
__device__ __align__(16) float g_cw[EMAX];
__device__ __align__(16) float g_crow[OUTC];

__device__ __forceinline__ int clampi(int v, int n) {
    return (v < 0) ? 0 : ((v >= n) ? n - 1 : v);
}

// ---------------------------------------------------------------------------
// CSR build
// ---------------------------------------------------------------------------
__global__ void k_zero(int n) {
    int i = blockIdx.x * blockDim.x + threadIdx.x;
    if (i < n) { g_degcnt[i] = 0u; g_fill[i] = 0; }
}

__global__ void k_count_deg(const int* __restrict__ dst, int E, int n) {
    int e = blockIdx.x * blockDim.x + threadIdx.x;
    if (e < E) atomicAdd(&g_degcnt[clampi(dst[e], n)], 1u);
}

__global__ void k_finalize_deg(int n) {
    int i = blockIdx.x * blockDim.x + threadIdx.x;
    if (i < n) g_disqrt[i] = rsqrtf(1.0f + (float)g_degcnt[i]);  // +1 self loop
}

// Single-block exclusive scan of g_degcnt -> g_rowptr (n up to ~50k).
__global__ void k_scan(int n) {
    __shared__ int warp_sums[32];
    __shared__ int s_carry;
    const int tid = threadIdx.x;
    const int lane = tid & 31, wid = tid >> 5;
    if (tid == 0) s_carry = 0;
    __syncthreads();

    for (int base = 0; base < n; base += 1024) {
        int i = base + tid;
        int v = (i < n) ? (int)g_degcnt[i] : 0;
        int x = v;
        #pragma unroll
        for (int o = 1; o < 32; o <<= 1) {
            int y = __shfl_up_sync(0xffffffffu, x, o);
            if (lane >= o) x += y;
        }
        if (lane == 31) warp_sums[wid] = x;
        __syncthreads();
        if (wid == 0) {
            int s = warp_sums[lane];
            #pragma unroll
            for (int o = 1; o < 32; o <<= 1) {
                int y = __shfl_up_sync(0xffffffffu, s, o);
                if (lane >= o) s += y;
            }
            warp_sums[lane] = s;   // inclusive across warps
        }
        __syncthreads();
        int excl = s_carry + (x - v) + (wid > 0 ? warp_sums[wid - 1] : 0);
        if (i < n) g_rowptr[i] = excl;
        __syncthreads();
        if (tid == 0) s_carry += warp_sums[31];
        __syncthreads();
    }
    if (tid == 0) g_rowptr[n] = s_carry;   // == E
}

// Fill CSR: position via per-dst int counter (int atomics only).
__global__ void k_fill(const int* __restrict__ src,
                       const int* __restrict__ dst, int E, int n) {
    int e = blockIdx.x * blockDim.x + threadIdx.x;
    if (e < E) {
        int s = clampi(src[e], n);
        int d = clampi(dst[e], n);
        int pos = g_rowptr[d] + atomicAdd(&g_fill[d], 1);
        g_csrc[pos] = s;
        g_cw[pos]   = g_disqrt[s] * g_disqrt[d];
    }
}

// Constant classifier row: crow[j] = bc[j] + sum_t text[t] * Wc[(HID+t), j]
__global__ void k_crow(const float* __restrict__ Wc, const float* __restrict__ bc,
                       const float* __restrict__ text) {
    int j = blockIdx.x * blockDim.x + threadIdx.x;
    if (j < OUTC) {
        float s = bc[j];
        for (int t = 0; t < TEXTD; t++)
            s += text[t] * Wc[(size_t)(HID + t) * OUTC + j];
        g_crow[j] = s;
    }
}

// ---------------------------------------------------------------------------
// Atomic-free aggregation: one warp per node, lane owns 4 channels.
// out[i,:] = [relu]( h[i,:]*disqrt[i]^2 + bias + sum_{e: dst=i} h[src_e,:]*w_e )
// ---------------------------------------------------------------------------
__device__ __forceinline__ void aggregate_body(
    const float* __restrict__ h, float* __restrict__ o,
    const float* __restrict__ bias, int relu, int N)
{
    const float4* h4 = (const float4*)h;
    float4*       o4 = (float4*)o;

    int node = (blockIdx.x * blockDim.x + threadIdx.x) >> 5;
    if (node >= N) return;
    int lane = threadIdx.x & 31;

    int beg = g_rowptr[node];
    int end = g_rowptr[node + 1];
    float dw = g_disqrt[node];
    float dw2 = dw * dw;

    float4 b = ((const float4*)bias)[lane];
    float4 acc = h4[(size_t)node * 32 + lane];
    acc.x = acc.x * dw2 + b.x;  acc.y = acc.y * dw2 + b.y;
    acc.z = acc.z * dw2 + b.z;  acc.w = acc.w * dw2 + b.w;

    int j = beg;
    for (; j + 4 <= end; j += 4) {
        int   s0 = g_csrc[j],   s1 = g_csrc[j+1], s2 = g_csrc[j+2], s3 = g_csrc[j+3];
        float w0 = g_cw[j],     w1 = g_cw[j+1],   w2 = g_cw[j+2],   w3 = g_cw[j+3];
        float4 v0 = h4[(size_t)s0 * 32 + lane];
        float4 v1 = h4[(size_t)s1 * 32 + lane];
        float4 v2 = h4[(size_t)s2 * 32 + lane];
        float4 v3 = h4[(size_t)s3 * 32 + lane];
        acc.x += v0.x*w0 + v1.x*w1 + v2.x*w2 + v3.x*w3;
        acc.y += v0.y*w0 + v1.y*w1 + v2.y*w2 + v3.y*w3;
        acc.z += v0.z*w0 + v1.z*w1 + v2.z*w2 + v3.z*w3;
        acc.w += v0.w*w0 + v1.w*w1 + v2.w*w2 + v3.w*w3;
    }
    for (; j < end; j++) {
        int s = g_csrc[j];
        float w = g_cw[j];
        float4 v = h4[(size_t)s * 32 + lane];
        acc.x += v.x*w; acc.y += v.y*w; acc.z += v.z*w; acc.w += v.w*w;
    }

    if (relu) {
        acc.x = fmaxf(acc.x, 0.f); acc.y = fmaxf(acc.y, 0.f);
        acc.z = fmaxf(acc.z, 0.f); acc.w = fmaxf(acc.w, 0.f);
    }
    o4[(size_t)node * 32 + lane] = acc;
}

__global__ __launch_bounds__(256) void k_agg1(const float* __restrict__ bias, int N) {
    aggregate_body(g_h1, g_agg1, bias, 1, N);
}
__global__ __launch_bounds__(256) void k_agg2(const float* __restrict__ bias, int N) {
    aggregate_body(g_h2, g_agg2, bias, 0, N);
}

// ---------------------------------------------------------------------------
// Tiled fp32 GEMM body: C[M,N] = A[M,K] @ B[K,N] (+ biasRow[j])
// 128x128 tile, BK=8, 256 threads, 8x8/thread.
// Requires K % 8 == 0, N % 4 == 0, 16B-aligned rows (holds for all 3 calls).
// ---------------------------------------------------------------------------
__device__ __forceinline__ void sgemm_body(
    const float* __restrict__ A, const float* __restrict__ B, float* __restrict__ C,
    int M, int N, int K, int lda, int ldb, int ldc,
    const float* __restrict__ biasRow)
{
    __shared__ float As[8][128];
    __shared__ float Bs[8][128];

    const int tid = threadIdx.x;
    const int tx  = tid & 15;
    const int ty  = tid >> 4;
    const int bm  = blockIdx.y * 128;
    const int bn  = blockIdx.x * 128;

    const int arow = tid >> 1;
    const int acol = (tid & 1) * 4;
    const int brow = tid >> 5;
    const int bcol = (tid & 31) * 4;

    float acc[8][8];
    #pragma unroll
    for (int i = 0; i < 8; i++)
        #pragma unroll
        for (int j = 0; j < 8; j++) acc[i][j] = 0.0f;

    for (int k0 = 0; k0 < K; k0 += 8) {
        float4 av = make_float4(0.f, 0.f, 0.f, 0.f);
        int gr = bm + arow;
        if (gr < M)
            av = *(const float4*)(A + (size_t)gr * lda + k0 + acol);
        As[acol + 0][arow] = av.x;
        As[acol + 1][arow] = av.y;
        As[acol + 2][arow] = av.z;
        As[acol + 3][arow] = av.w;

        float4 bv = make_float4(0.f, 0.f, 0.f, 0.f);
        int gc = bn + bcol;
        if (gc < N)
            bv = *(const float4*)(B + (size_t)(k0 + brow) * ldb + gc);
        *(float4*)&Bs[brow][bcol] = bv;

        __syncthreads();

        #pragma unroll
        for (int k = 0; k < 8; k++) {
            float a[8], b[8];
            #pragma unroll
            for (int i = 0; i < 8; i++) a[i] = As[k][ty + 16 * i];
            #pragma unroll
            for (int j = 0; j < 8; j++) b[j] = Bs[k][tx + 16 * j];
            #pragma unroll
            for (int i = 0; i < 8; i++)
                #pragma unroll
                for (int j = 0; j < 8; j++) acc[i][j] += a[i] * b[j];
        }
        __syncthreads();
    }

    #pragma unroll
    for (int i = 0; i < 8; i++) {
        int r = bm + ty + 16 * i;
        if (r < M) {
            #pragma unroll
            for (int j = 0; j < 8; j++) {
                int c = bn + tx + 16 * j;
                if (c < N) {
                    float v = acc[i][j];
                    if (biasRow) v += biasRow[c];
                    C[(size_t)r * ldc + c] = v;
                }
            }
        }
    }
}

// GEMM wrappers binding device-global scratch directly.
__global__ __launch_bounds__(256) void k_gemm1(const float* __restrict__ x,
                                               const float* __restrict__ W1, int M) {
    sgemm_body(x, W1, g_h1, M, HID, INCH, INCH, HID, HID, nullptr);
}
__global__ __launch_bounds__(256) void k_gemm2(const float* __restrict__ W2, int M) {
    sgemm_body(g_agg1, W2, g_h2, M, HID, HID, HID, HID, HID, nullptr);
}
__global__ __launch_bounds__(256) void k_gemm3(const float* __restrict__ Wc,
                                               float* __restrict__ out, int M) {
    sgemm_body(g_agg2, Wc, out, M, OUTC, HID, HID, OUTC, OUTC, g_crow);
}

// ---------------------------------------------------------------------------
// Launch
// ---------------------------------------------------------------------------
extern "C" void kernel_launch(void* const* d_in, const int* in_sizes, int n_in,
                              void* d_out, int out_size)
{
    // Bind inputs by element count (unique except the two 128-length biases,
    // which are tie-broken by order: b1 first, then b2).
    const float *x = 0, *text = 0, *W1 = 0, *b1 = 0, *W2 = 0, *b2 = 0, *Wc = 0, *bc = 0;
    const int   *ei = 0;
    int nbias = 0;
    for (int i = 0; i < n_in; i++) {
        int sz = in_sizes[i];
        if      (sz == NMAX * INCH)          x    = (const float*)d_in[i];
        else if (sz == 2 * EMAX)             ei   = (const int*)d_in[i];
        else if (sz == TEXTD)                text = (const float*)d_in[i];
        else if (sz == INCH * HID)           W1   = (const float*)d_in[i];
        else if (sz == HID * HID)            W2   = (const float*)d_in[i];
        else if (sz == (HID + TEXTD) * OUTC) Wc   = (const float*)d_in[i];
        else if (sz == OUTC)                 bc   = (const float*)d_in[i];
        else if (sz == HID) {
            if (nbias++ == 0) b1 = (const float*)d_in[i];
            else              b2 = (const float*)d_in[i];
        }
    }
    float* out = (float*)d_out;

    const int N = NMAX;
    const int E = EMAX;
    const int* src = ei;        // edge_index row 0
    const int* dst = ei + E;    // edge_index row 1

    const int T = 256;

    // CSR build
    k_zero<<<(N + T - 1) / T, T>>>(N);
    k_count_deg<<<(E + T - 1) / T, T>>>(dst, E, N);
    k_finalize_deg<<<(N + T - 1) / T, T>>>(N);
    k_scan<<<1, 1024>>>(N);
    k_fill<<<(E + T - 1) / T, T>>>(src, dst, E, N);

    // constant classifier row
    k_crow<<<(OUTC + T - 1) / T, T>>>(Wc, bc, text);

    const int aggBlocks = (N * 32 + T - 1) / T;   // warp per node
    dim3 gridH((HID + 127) / 128, (N + 127) / 128);
    dim3 gridC((OUTC + 127) / 128, (N + 127) / 128);

    // layer 1
    k_gemm1<<<gridH, T>>>(x, W1, N);
    k_agg1<<<aggBlocks, T>>>(b1, N);

    // layer 2
    k_gemm2<<<gridH, T>>>(W2, N);
    k_agg2<<<aggBlocks, T>>>(b2, N);

    // classifier
    k_gemm3<<<gridC, T>>>(Wc, out, N);
}

// round 7
// speedup vs baseline: 1.2694x; 1.2694x over previous
#include <cuda_runtime.h>
#include <cstdint>

// ---------------------------------------------------------------------------
// GCN plugin: 2x GCNConv (symmetric norm, self loops) + text-concat classifier
//   h1 = x @ W1;  agg1 = relu(CSR-aggregate(h1) + selfloop + b1)
//   h2 = agg1 @ W2; agg2 = CSR-aggregate(h2) + selfloop + b2
//   logits = agg2 @ Wc[:128] + (bc + text @ Wc[128:])   <- text term constant
// Aggregation is atomic-free CSR warp-per-node gather. Classifier GEMM runs
// on tensor cores (tf32 mma.sync m16n8k8); layers 1/2 stay fp32 SIMT so tf32
// rounding does not compound. (Resubmission: R6 never ran — broker failure.)
// ---------------------------------------------------------------------------

#define NMAX   50000
#define INCH   256
#define HID    128
#define OUTC   1000
#define TEXTD  768
#define EMAX   800000

__device__ __align__(16) float g_h1[NMAX * HID];
__device__ __align__(16) float g_agg1[NMAX * HID];
__device__ __align__(16) float g_h2[NMAX * HID];
__device__ __align__(16) float g_agg2[NMAX * HID];
__device__ __align__(16) float g_disqrt[NMAX];
__device__ unsigned int        g_degcnt[NMAX];
__device__ int                 g_rowptr[NMAX + 1];
__device__ int                 g_fill[NMAX];
__device__ __align__(16) int   g_csrc[EMAX];
__device__ __align__(16) float g_cw[EMAX];
__device__ __align__(16) float g_crow[OUTC];

__device__ __forceinline__ int clampi(int v, int n) {
    return (v < 0) ? 0 : ((v >= n) ? n - 1 : v);
}

// ---------------------------------------------------------------------------
// CSR build
// ---------------------------------------------------------------------------
__global__ void k_zero(int n) {
    int i = blockIdx.x * blockDim.x + threadIdx.x;
    if (i < n) { g_degcnt[i] = 0u; g_fill[i] = 0; }
}

__global__ void k_count_deg(const int* __restrict__ dst, int E, int n) {
    int e = blockIdx.x * blockDim.x + threadIdx.x;
    if (e < E) atomicAdd(&g_degcnt[clampi(dst[e], n)], 1u);
}

__global__ void k_finalize_deg(int n) {
    int i = blockIdx.x * blockDim.x + threadIdx.x;
    if (i < n) g_disqrt[i] = rsqrtf(1.0f + (float)g_degcnt[i]);  // +1 self loop
}

// Parallel exclusive scan: 1024 threads, chunk-per-thread + block scan.
__global__ void k_scan(int n) {
    __shared__ int wsum[32];
    const int t = threadIdx.x;
    const int lane = t & 31, wid = t >> 5;
    const int chunk = (n + 1023) >> 10;
    int lo = t * chunk;       if (lo > n) lo = n;
    int hi = lo + chunk;      if (hi > n) hi = n;

    int sum = 0;
    for (int i = lo; i < hi; i++) sum += (int)g_degcnt[i];

    int x = sum;
    #pragma unroll
    for (int o = 1; o < 32; o <<= 1) {
        int y = __shfl_up_sync(0xffffffffu, x, o);
        if (lane >= o) x += y;
    }
    if (lane == 31) wsum[wid] = x;
    __syncthreads();
    if (wid == 0) {
        int s = wsum[lane];
        #pragma unroll
        for (int o = 1; o < 32; o <<= 1) {
            int y = __shfl_up_sync(0xffffffffu, s, o);
            if (lane >= o) s += y;
        }
        wsum[lane] = s;
    }
    __syncthreads();

    int run = (x - sum) + (wid > 0 ? wsum[wid - 1] : 0);
    for (int i = lo; i < hi; i++) {
        g_rowptr[i] = run;
        run += (int)g_degcnt[i];
    }
    if (hi == n) g_rowptr[n] = run;   // == E (same value from all clamped threads)
}

__global__ void k_fill(const int* __restrict__ src,
                       const int* __restrict__ dst, int E, int n) {
    int e = blockIdx.x * blockDim.x + threadIdx.x;
    if (e < E) {
        int s = clampi(src[e], n);
        int d = clampi(dst[e], n);
        int pos = g_rowptr[d] + atomicAdd(&g_fill[d], 1);
        g_csrc[pos] = s;
        g_cw[pos]   = g_disqrt[s] * g_disqrt[d];
    }
}

// Constant classifier row: crow[j] = bc[j] + sum_t text[t] * Wc[(HID+t), j]
__global__ void k_crow(const float* __restrict__ Wc, const float* __restrict__ bc,
                       const float* __restrict__ text) {
    int j = blockIdx.x * blockDim.x + threadIdx.x;
    if (j < OUTC) {
        float s = bc[j];
        for (int t = 0; t < TEXTD; t++)
            s += text[t] * Wc[(size_t)(HID + t) * OUTC + j];
        g_crow[j] = s;
    }
}

// ---------------------------------------------------------------------------
// Atomic-free aggregation: one warp per node, lane owns 4 channels.
// ---------------------------------------------------------------------------
__device__ __forceinline__ void aggregate_body(
    const float* __restrict__ h, float* __restrict__ o,
    const float* __restrict__ bias, int relu, int N)
{
    const float4* h4 = (const float4*)h;
    float4*       o4 = (float4*)o;

    int node = (blockIdx.x * blockDim.x + threadIdx.x) >> 5;
    if (node >= N) return;
    int lane = threadIdx.x & 31;

    int beg = g_rowptr[node];
    int end = g_rowptr[node + 1];
    float dw = g_disqrt[node];
    float dw2 = dw * dw;

    float4 b = ((const float4*)bias)[lane];
    float4 acc = h4[(size_t)node * 32 + lane];
    acc.x = acc.x * dw2 + b.x;  acc.y = acc.y * dw2 + b.y;
    acc.z = acc.z * dw2 + b.z;  acc.w = acc.w * dw2 + b.w;

    int j = beg;
    for (; j + 4 <= end; j += 4) {
        int   s0 = g_csrc[j],   s1 = g_csrc[j+1], s2 = g_csrc[j+2], s3 = g_csrc[j+3];
        float w0 = g_cw[j],     w1 = g_cw[j+1],   w2 = g_cw[j+2],   w3 = g_cw[j+3];
        float4 v0 = h4[(size_t)s0 * 32 + lane];
        float4 v1 = h4[(size_t)s1 * 32 + lane];
        float4 v2 = h4[(size_t)s2 * 32 + lane];
        float4 v3 = h4[(size_t)s3 * 32 + lane];
        acc.x += v0.x*w0 + v1.x*w1 + v2.x*w2 + v3.x*w3;
        acc.y += v0.y*w0 + v1.y*w1 + v2.y*w2 + v3.y*w3;
        acc.z += v0.z*w0 + v1.z*w1 + v2.z*w2 + v3.z*w3;
        acc.w += v0.w*w0 + v1.w*w1 + v2.w*w2 + v3.w*w3;
    }
    for (; j < end; j++) {
        int s = g_csrc[j];
        float w = g_cw[j];
        float4 v = h4[(size_t)s * 32 + lane];
        acc.x += v.x*w; acc.y += v.y*w; acc.z += v.z*w; acc.w += v.w*w;
    }

    if (relu) {
        acc.x = fmaxf(acc.x, 0.f); acc.y = fmaxf(acc.y, 0.f);
        acc.z = fmaxf(acc.z, 0.f); acc.w = fmaxf(acc.w, 0.f);
    }
    o4[(size_t)node * 32 + lane] = acc;
}

__global__ __launch_bounds__(256) void k_agg1(const float* __restrict__ bias, int N) {
    aggregate_body(g_h1, g_agg1, bias, 1, N);
}
__global__ __launch_bounds__(256) void k_agg2(const float* __restrict__ bias, int N) {
    aggregate_body(g_h2, g_agg2, bias, 0, N);
}

// ---------------------------------------------------------------------------
// fp32 SIMT GEMM (layers 1 & 2): C[M,N] = A[M,K] @ B[K,N]
// ---------------------------------------------------------------------------
__device__ __forceinline__ void sgemm_body(
    const float* __restrict__ A, const float* __restrict__ B, float* __restrict__ C,
    int M, int N, int K, int lda, int ldb, int ldc)
{
    __shared__ float As[8][128];
    __shared__ float Bs[8][128];

    const int tid = threadIdx.x;
    const int tx  = tid & 15;
    const int ty  = tid >> 4;
    const int bm  = blockIdx.y * 128;
    const int bn  = blockIdx.x * 128;

    const int arow = tid >> 1;
    const int acol = (tid & 1) * 4;
    const int brow = tid >> 5;
    const int bcol = (tid & 31) * 4;

    float acc[8][8];
    #pragma unroll
    for (int i = 0; i < 8; i++)
        #pragma unroll
        for (int j = 0; j < 8; j++) acc[i][j] = 0.0f;

    for (int k0 = 0; k0 < K; k0 += 8) {
        float4 av = make_float4(0.f, 0.f, 0.f, 0.f);
        int gr = bm + arow;
        if (gr < M)
            av = *(const float4*)(A + (size_t)gr * lda + k0 + acol);
        As[acol + 0][arow] = av.x;
        As[acol + 1][arow] = av.y;
        As[acol + 2][arow] = av.z;
        As[acol + 3][arow] = av.w;

        float4 bv = make_float4(0.f, 0.f, 0.f, 0.f);
        int gc = bn + bcol;
        if (gc < N)
            bv = *(const float4*)(B + (size_t)(k0 + brow) * ldb + gc);
        *(float4*)&Bs[brow][bcol] = bv;

        __syncthreads();

        #pragma unroll
        for (int k = 0; k < 8; k++) {
            float a[8], b[8];
            #pragma unroll
            for (int i = 0; i < 8; i++) a[i] = As[k][ty + 16 * i];
            #pragma unroll
            for (int j = 0; j < 8; j++) b[j] = Bs[k][tx + 16 * j];
            #pragma unroll
            for (int i = 0; i < 8; i++)
                #pragma unroll
                for (int j = 0; j < 8; j++) acc[i][j] += a[i] * b[j];
        }
        __syncthreads();
    }

    #pragma unroll
    for (int i = 0; i < 8; i++) {
        int r = bm + ty + 16 * i;
        if (r < M) {
            #pragma unroll
            for (int j = 0; j < 8; j++) {
                int c = bn + tx + 16 * j;
                if (c < N) C[(size_t)r * ldc + c] = acc[i][j];
            }
        }
    }
}

__global__ __launch_bounds__(256) void k_gemm1(const float* __restrict__ x,
                                               const float* __restrict__ W1, int M) {
    sgemm_body(x, W1, g_h1, M, HID, INCH, INCH, HID, HID);
}
__global__ __launch_bounds__(256) void k_gemm2(const float* __restrict__ W2, int M) {
    sgemm_body(g_agg1, W2, g_h2, M, HID, HID, HID, HID, HID);
}

// ---------------------------------------------------------------------------
// Classifier GEMM on tensor cores: out[M,OUTC] = g_agg2[M,128] @ Wc[:128] + crow
// tf32 mma.sync.m16n8k8. Block 128x128, BK=16, 8 warps (4m x 2n), warp 32x64.
// ---------------------------------------------------------------------------
__device__ __forceinline__ uint32_t f2tf32(float f) {
    uint32_t r;
    asm("cvt.rna.tf32.f32 %0, %1;" : "=r"(r) : "f"(f));
    return r;
}

__global__ __launch_bounds__(256) void k_gemm3_tf32(const float* __restrict__ Wc,
                                                    float* __restrict__ out, int M)
{
    __shared__ uint32_t As[128][20];    // stride 20: a-frag LDS conflict-free
    __shared__ uint32_t Bs[16][136];    // stride 136: b-frag LDS conflict-free

    const int tid  = threadIdx.x;
    const int lane = tid & 31;
    const int warp = tid >> 5;
    const int wm   = warp & 3;          // 0..3 -> m offset wm*32
    const int wn   = warp >> 2;         // 0..1 -> n offset wn*64
    const int bm   = blockIdx.y * 128;
    const int bn   = blockIdx.x * 128;
    const int g    = lane >> 2;         // group 0..7
    const int tg   = lane & 3;          // thread-in-group 0..3

    float acc[2][8][4];
    #pragma unroll
    for (int i = 0; i < 2; i++)
        #pragma unroll
        for (int j = 0; j < 8; j++)
            #pragma unroll
            for (int r = 0; r < 4; r++) acc[i][j][r] = 0.0f;

    for (int k0 = 0; k0 < HID; k0 += 16) {
        // A tile: 128 rows x 16 cols of g_agg2
        #pragma unroll
        for (int q = tid; q < 512; q += 256) {
            int row = q >> 2, quad = (q & 3) * 4;
            int gr = bm + row;
            float4 v = make_float4(0.f, 0.f, 0.f, 0.f);
            if (gr < M)
                v = *(const float4*)(g_agg2 + (size_t)gr * HID + k0 + quad);
            As[row][quad + 0] = f2tf32(v.x);
            As[row][quad + 1] = f2tf32(v.y);
            As[row][quad + 2] = f2tf32(v.z);
            As[row][quad + 3] = f2tf32(v.w);
        }
        // B tile: 16 rows x 128 cols of Wc (rows k0..k0+15)
        #pragma unroll
        for (int q = tid; q < 512; q += 256) {
            int row = q >> 5, c4 = (q & 31) * 4;
            int gc = bn + c4;
            float4 v = make_float4(0.f, 0.f, 0.f, 0.f);
            if (gc + 3 < OUTC)
                v = *(const float4*)(Wc + (size_t)(k0 + row) * OUTC + gc);
            Bs[row][c4 + 0] = f2tf32(v.x);
            Bs[row][c4 + 1] = f2tf32(v.y);
            Bs[row][c4 + 2] = f2tf32(v.z);
            Bs[row][c4 + 3] = f2tf32(v.w);
        }
        __syncthreads();

        #pragma unroll
        for (int ka = 0; ka < 16; ka += 8) {
            uint32_t a[2][4];
            #pragma unroll
            for (int i = 0; i < 2; i++) {
                int rb = wm * 32 + i * 16 + g;
                a[i][0] = As[rb][ka + tg];
                a[i][1] = As[rb + 8][ka + tg];
                a[i][2] = As[rb][ka + tg + 4];
                a[i][3] = As[rb + 8][ka + tg + 4];
            }
            #pragma unroll
            for (int j = 0; j < 8; j++) {
                int nb = wn * 64 + j * 8 + g;
                uint32_t b0 = Bs[ka + tg][nb];
                uint32_t b1 = Bs[ka + tg + 4][nb];
                #pragma unroll
                for (int i = 0; i < 2; i++) {
                    asm volatile(
                        "mma.sync.aligned.m16n8k8.row.col.f32.tf32.tf32.f32 "
                        "{%0,%1,%2,%3}, {%4,%5,%6,%7}, {%8,%9}, {%0,%1,%2,%3};"
                        : "+f"(acc[i][j][0]), "+f"(acc[i][j][1]),
                          "+f"(acc[i][j][2]), "+f"(acc[i][j][3])
                        : "r"(a[i][0]), "r"(a[i][1]), "r"(a[i][2]), "r"(a[i][3]),
                          "r"(b0), "r"(b1));
                }
            }
        }
        __syncthreads();
    }

    // Epilogue: c0,c1 -> (row g, cols 2tg,2tg+1); c2,c3 -> row g+8.
    #pragma unroll
    for (int i = 0; i < 2; i++) {
        int r0 = bm + wm * 32 + i * 16 + g;
        #pragma unroll
        for (int j = 0; j < 8; j++) {
            int c = bn + wn * 64 + j * 8 + 2 * tg;
            if (c + 1 < OUTC) {
                float cb0 = g_crow[c], cb1 = g_crow[c + 1];
                if (r0 < M) {
                    out[(size_t)r0 * OUTC + c]     = acc[i][j][0] + cb0;
                    out[(size_t)r0 * OUTC + c + 1] = acc[i][j][1] + cb1;
                }
                if (r0 + 8 < M) {
                    out[(size_t)(r0 + 8) * OUTC + c]     = acc[i][j][2] + cb0;
                    out[(size_t)(r0 + 8) * OUTC + c + 1] = acc[i][j][3] + cb1;
                }
            }
        }
    }
}

// ---------------------------------------------------------------------------
// Launch
// ---------------------------------------------------------------------------
extern "C" void kernel_launch(void* const* d_in, const int* in_sizes, int n_in,
                              void* d_out, int out_size)
{
    const float *x = 0, *text = 0, *W1 = 0, *b1 = 0, *W2 = 0, *b2 = 0, *Wc = 0, *bc = 0;
    const int   *ei = 0;
    int nbias = 0;
    for (int i = 0; i < n_in; i++) {
        int sz = in_sizes[i];
        if      (sz == NMAX * INCH)          x    = (const float*)d_in[i];
        else if (sz == 2 * EMAX)             ei   = (const int*)d_in[i];
        else if (sz == TEXTD)                text = (const float*)d_in[i];
        else if (sz == INCH * HID)           W1   = (const float*)d_in[i];
        else if (sz == HID * HID)            W2   = (const float*)d_in[i];
        else if (sz == (HID + TEXTD) * OUTC) Wc   = (const float*)d_in[i];
        else if (sz == OUTC)                 bc   = (const float*)d_in[i];
        else if (sz == HID) {
            if (nbias++ == 0) b1 = (const float*)d_in[i];
            else              b2 = (const float*)d_in[i];
        }
    }
    float* out = (float*)d_out;

    const int N = NMAX;
    const int E = EMAX;
    const int* src = ei;
    const int* dst = ei + E;

    const int T = 256;

    // CSR build
    k_zero<<<(N + T - 1) / T, T>>>(N);
    k_count_deg<<<(E + T - 1) / T, T>>>(dst, E, N);
    k_finalize_deg<<<(N + T - 1) / T, T>>>(N);
    k_scan<<<1, 1024>>>(N);
    k_fill<<<(E + T - 1) / T, T>>>(src, dst, E, N);

    // constant classifier row
    k_crow<<<(OUTC + T - 1) / T, T>>>(Wc, bc, text);

    const int aggBlocks = (N * 32 + T - 1) / T;
    dim3 gridH((HID + 127) / 128, (N + 127) / 128);
    dim3 gridC((OUTC + 127) / 128, (N + 127) / 128);

    // layer 1
    k_gemm1<<<gridH, T>>>(x, W1, N);
    k_agg1<<<aggBlocks, T>>>(b1, N);

    // layer 2
    k_gemm2<<<gridH, T>>>(W2, N);
    k_agg2<<<aggBlocks, T>>>(b2, N);

    // classifier (tensor cores)
    k_gemm3_tf32<<<gridC, T>>>(Wc, out, N);
}

// round 8
// speedup vs baseline: 1.6346x; 1.2877x over previous
#include <cuda_runtime.h>
#include <cstdint>

// ---------------------------------------------------------------------------
// GCN plugin: 2x GCNConv (symmetric norm, self loops) + text-concat classifier
//   h1 = x @ W1;  agg1 = relu(CSR-aggregate(h1) + selfloop + b1)
//   h2 = agg1 @ W2; agg2 = CSR-aggregate(h2) + selfloop + b2
//   logits = agg2 @ Wc[:128] + (bc + text @ Wc[128:])   <- text term constant
// All three GEMMs on tensor cores (tf32 mma.sync m16n8k8). Aggregation is
// atomic-free CSR warp-per-node gather. Scan is 3-phase coalesced.
// ---------------------------------------------------------------------------

#define NMAX   50000
#define INCH   256
#define HID    128
#define OUTC   1000
#define TEXTD  768
#define EMAX   800000
#define SEG    1024
#define NSEG   ((NMAX + SEG - 1) / SEG)   // 49

__device__ __align__(16) float g_h1[NMAX * HID];
__device__ __align__(16) float g_agg1[NMAX * HID];
__device__ __align__(16) float g_h2[NMAX * HID];
__device__ __align__(16) float g_agg2[NMAX * HID];
__device__ __align__(16) float g_disqrt[NMAX];
__device__ unsigned int        g_degcnt[NMAX];
__device__ int                 g_rowptr[NMAX + 1];
__device__ int                 g_fill[NMAX];
__device__ __align__(16) int   g_csrc[EMAX];
__device__ __align__(16) float g_cw[EMAX];
__device__ __align__(16) float g_crow[OUTC];
__device__ int                 g_psum[64];
__device__ int                 g_poff[64];

__device__ __forceinline__ int clampi(int v, int n) {
    return (v < 0) ? 0 : ((v >= n) ? n - 1 : v);
}

// ---------------------------------------------------------------------------
// CSR build
// ---------------------------------------------------------------------------
__global__ void k_zero(int n) {
    int i = blockIdx.x * blockDim.x + threadIdx.x;
    if (i < n) { g_degcnt[i] = 0u; g_fill[i] = 0; }
}

__global__ void k_count_deg(const int* __restrict__ dst, int E, int n) {
    int e = blockIdx.x * blockDim.x + threadIdx.x;
    if (e < E) atomicAdd(&g_degcnt[clampi(dst[e], n)], 1u);
}

__global__ void k_finalize_deg(int n) {
    int i = blockIdx.x * blockDim.x + threadIdx.x;
    if (i < n) g_disqrt[i] = rsqrtf(1.0f + (float)g_degcnt[i]);  // +1 self loop
}

// Scan phase 1: per-segment sums (coalesced, one element per thread).
__global__ void k_scan1(int n) {
    __shared__ int ws[32];
    int b = blockIdx.x, t = threadIdx.x;
    int lane = t & 31, wid = t >> 5;
    int i = b * SEG + t;
    int v = (i < n) ? (int)g_degcnt[i] : 0;
    #pragma unroll
    for (int o = 16; o; o >>= 1) v += __shfl_down_sync(0xffffffffu, v, o);
    if (lane == 0) ws[wid] = v;
    __syncthreads();
    if (wid == 0) {
        int s = (lane < (int)(blockDim.x >> 5)) ? ws[lane] : 0;
        #pragma unroll
        for (int o = 16; o; o >>= 1) s += __shfl_down_sync(0xffffffffu, s, o);
        if (lane == 0) g_psum[b] = s;
    }
}

// Scan phase 2: exclusive scan of <=64 segment sums. 64 threads.
__global__ void k_scan2(int nb, int n) {
    __shared__ int sh[64];
    int t = threadIdx.x;
    sh[t] = (t < nb) ? g_psum[t] : 0;
    __syncthreads();
    for (int o = 1; o < 64; o <<= 1) {
        int y = (t >= o) ? sh[t - o] : 0;
        __syncthreads();
        sh[t] += y;
        __syncthreads();
    }
    if (t < nb) g_poff[t] = t ? sh[t - 1] : 0;
    if (t == 0) g_rowptr[n] = sh[63];   // total == E
}

// Scan phase 3: per-segment local exclusive scan + segment offset.
__global__ void k_scan3(int n) {
    __shared__ int ws[32];
    int b = blockIdx.x, t = threadIdx.x;
    int lane = t & 31, wid = t >> 5;
    int i = b * SEG + t;
    int v = (i < n) ? (int)g_degcnt[i] : 0;
    int x = v;
    #pragma unroll
    for (int o = 1; o < 32; o <<= 1) {
        int y = __shfl_up_sync(0xffffffffu, x, o);
        if (lane >= o) x += y;
    }
    if (lane == 31) ws[wid] = x;
    __syncthreads();
    if (wid == 0) {
        int s = ws[lane];
        #pragma unroll
        for (int o = 1; o < 32; o <<= 1) {
            int y = __shfl_up_sync(0xffffffffu, s, o);
            if (lane >= o) s += y;
        }
        ws[lane] = s;
    }
    __syncthreads();
    int excl = (x - v) + (wid ? ws[wid - 1] : 0) + g_poff[b];
    if (i < n) g_rowptr[i] = excl;
}

__global__ void k_fill(const int* __restrict__ src,
                       const int* __restrict__ dst, int E, int n) {
    int e = blockIdx.x * blockDim.x + threadIdx.x;
    if (e < E) {
        int s = clampi(src[e], n);
        int d = clampi(dst[e], n);
        int pos = g_rowptr[d] + atomicAdd(&g_fill[d], 1);
        g_csrc[pos] = s;
        g_cw[pos]   = g_disqrt[s] * g_disqrt[d];
    }
}

// Constant classifier row: crow[j] = bc[j] + sum_t text[t] * Wc[(HID+t), j]
// Block: 32 columns x 8 row-groups, smem reduce.
__global__ void k_crow(const float* __restrict__ Wc, const float* __restrict__ bc,
                       const float* __restrict__ text) {
    __shared__ float sh[8][32];
    int t  = threadIdx.x;          // 256
    int cl = t & 31, rg = t >> 5;
    int col = blockIdx.x * 32 + cl;
    float s = 0.f;
    if (col < OUTC)
        for (int r = rg; r < TEXTD; r += 8)
            s += text[r] * Wc[(size_t)(HID + r) * OUTC + col];
    sh[rg][cl] = s;
    __syncthreads();
    if (rg == 0 && col < OUTC) {
        float tot = bc[col];
        #pragma unroll
        for (int k = 0; k < 8; k++) tot += sh[k][cl];
        g_crow[col] = tot;
    }
}

// ---------------------------------------------------------------------------
// Atomic-free aggregation: one warp per node, lane owns 4 channels.
// ---------------------------------------------------------------------------
__device__ __forceinline__ void aggregate_body(
    const float* __restrict__ h, float* __restrict__ o,
    const float* __restrict__ bias, int relu, int N)
{
    const float4* h4 = (const float4*)h;
    float4*       o4 = (float4*)o;

    int node = (blockIdx.x * blockDim.x + threadIdx.x) >> 5;
    if (node >= N) return;
    int lane = threadIdx.x & 31;

    int beg = g_rowptr[node];
    int end = g_rowptr[node + 1];
    float dw = g_disqrt[node];
    float dw2 = dw * dw;

    float4 b = ((const float4*)bias)[lane];
    float4 acc = h4[(size_t)node * 32 + lane];
    acc.x = acc.x * dw2 + b.x;  acc.y = acc.y * dw2 + b.y;
    acc.z = acc.z * dw2 + b.z;  acc.w = acc.w * dw2 + b.w;

    int j = beg;
    for (; j + 4 <= end; j += 4) {
        int   s0 = g_csrc[j],   s1 = g_csrc[j+1], s2 = g_csrc[j+2], s3 = g_csrc[j+3];
        float w0 = g_cw[j],     w1 = g_cw[j+1],   w2 = g_cw[j+2],   w3 = g_cw[j+3];
        float4 v0 = h4[(size_t)s0 * 32 + lane];
        float4 v1 = h4[(size_t)s1 * 32 + lane];
        float4 v2 = h4[(size_t)s2 * 32 + lane];
        float4 v3 = h4[(size_t)s3 * 32 + lane];
        acc.x += v0.x*w0 + v1.x*w1 + v2.x*w2 + v3.x*w3;
        acc.y += v0.y*w0 + v1.y*w1 + v2.y*w2 + v3.y*w3;
        acc.z += v0.z*w0 + v1.z*w1 + v2.z*w2 + v3.z*w3;
        acc.w += v0.w*w0 + v1.w*w1 + v2.w*w2 + v3.w*w3;
    }
    for (; j < end; j++) {
        int s = g_csrc[j];
        float w = g_cw[j];
        float4 v = h4[(size_t)s * 32 + lane];
        acc.x += v.x*w; acc.y += v.y*w; acc.z += v.z*w; acc.w += v.w*w;
    }

    if (relu) {
        acc.x = fmaxf(acc.x, 0.f); acc.y = fmaxf(acc.y, 0.f);
        acc.z = fmaxf(acc.z, 0.f); acc.w = fmaxf(acc.w, 0.f);
    }
    o4[(size_t)node * 32 + lane] = acc;
}

__global__ __launch_bounds__(256) void k_agg1(const float* __restrict__ bias, int N) {
    aggregate_body(g_h1, g_agg1, bias, 1, N);
}
__global__ __launch_bounds__(256) void k_agg2(const float* __restrict__ bias, int N) {
    aggregate_body(g_h2, g_agg2, bias, 0, N);
}

// ---------------------------------------------------------------------------
// Generic tf32 tensor-core GEMM: C[M,Nd] = A[M,K] @ B[K,Nd] (+ biasRow)
// mma.sync.m16n8k8. Block 128x128, BK=16, 8 warps (4m x 2n), warp 32x64.
// ldb = ldc = Nd. Requires K % 16 == 0, Nd % 4 == 0.
// ---------------------------------------------------------------------------
__device__ __forceinline__ uint32_t f2tf32(float f) {
    uint32_t r;
    asm("cvt.rna.tf32.f32 %0, %1;" : "=r"(r) : "f"(f));
    return r;
}

__global__ __launch_bounds__(256) void k_gemm_tf32(
    const float* __restrict__ A, int lda,
    const float* __restrict__ B,
    float* __restrict__ C,
    const float* __restrict__ biasRow,
    int M, int Nd, int K)
{
    __shared__ uint32_t As[128][20];    // stride 20: a-frag LDS conflict-free
    __shared__ uint32_t Bs[16][136];    // stride 136: b-frag LDS conflict-free

    const int tid  = threadIdx.x;
    const int lane = tid & 31;
    const int warp = tid >> 5;
    const int wm   = warp & 3;          // m offset wm*32
    const int wn   = warp >> 2;         // n offset wn*64
    const int bm   = blockIdx.y * 128;
    const int bn   = blockIdx.x * 128;
    const int g    = lane >> 2;         // group 0..7
    const int tg   = lane & 3;          // thread-in-group 0..3

    float acc[2][8][4];
    #pragma unroll
    for (int i = 0; i < 2; i++)
        #pragma unroll
        for (int j = 0; j < 8; j++)
            #pragma unroll
            for (int r = 0; r < 4; r++) acc[i][j][r] = 0.0f;

    for (int k0 = 0; k0 < K; k0 += 16) {
        // A tile: 128 rows x 16 cols
        #pragma unroll
        for (int q = tid; q < 512; q += 256) {
            int row = q >> 2, quad = (q & 3) * 4;
            int gr = bm + row;
            float4 v = make_float4(0.f, 0.f, 0.f, 0.f);
            if (gr < M)
                v = *(const float4*)(A + (size_t)gr * lda + k0 + quad);
            As[row][quad + 0] = f2tf32(v.x);
            As[row][quad + 1] = f2tf32(v.y);
            As[row][quad + 2] = f2tf32(v.z);
            As[row][quad + 3] = f2tf32(v.w);
        }
        // B tile: 16 rows x 128 cols
        #pragma unroll
        for (int q = tid; q < 512; q += 256) {
            int row = q >> 5, c4 = (q & 31) * 4;
            int gc = bn + c4;
            float4 v = make_float4(0.f, 0.f, 0.f, 0.f);
            if (gc + 3 < Nd)
                v = *(const float4*)(B + (size_t)(k0 + row) * Nd + gc);
            Bs[row][c4 + 0] = f2tf32(v.x);
            Bs[row][c4 + 1] = f2tf32(v.y);
            Bs[row][c4 + 2] = f2tf32(v.z);
            Bs[row][c4 + 3] = f2tf32(v.w);
        }
        __syncthreads();

        #pragma unroll
        for (int ka = 0; ka < 16; ka += 8) {
            uint32_t a[2][4];
            #pragma unroll
            for (int i = 0; i < 2; i++) {
                int rb = wm * 32 + i * 16 + g;
                a[i][0] = As[rb][ka + tg];
                a[i][1] = As[rb + 8][ka + tg];
                a[i][2] = As[rb][ka + tg + 4];
                a[i][3] = As[rb + 8][ka + tg + 4];
            }
            #pragma unroll
            for (int j = 0; j < 8; j++) {
                int nb = wn * 64 + j * 8 + g;
                uint32_t b0 = Bs[ka + tg][nb];
                uint32_t b1 = Bs[ka + tg + 4][nb];
                #pragma unroll
                for (int i = 0; i < 2; i++) {
                    asm volatile(
                        "mma.sync.aligned.m16n8k8.row.col.f32.tf32.tf32.f32 "
                        "{%0,%1,%2,%3}, {%4,%5,%6,%7}, {%8,%9}, {%0,%1,%2,%3};"
                        : "+f"(acc[i][j][0]), "+f"(acc[i][j][1]),
                          "+f"(acc[i][j][2]), "+f"(acc[i][j][3])
                        : "r"(a[i][0]), "r"(a[i][1]), "r"(a[i][2]), "r"(a[i][3]),
                          "r"(b0), "r"(b1));
                }
            }
        }
        __syncthreads();
    }

    // Epilogue: c0,c1 -> (row g, cols 2tg,2tg+1); c2,c3 -> row g+8.
    #pragma unroll
    for (int i = 0; i < 2; i++) {
        int r0 = bm + wm * 32 + i * 16 + g;
        #pragma unroll
        for (int j = 0; j < 8; j++) {
            int c = bn + wn * 64 + j * 8 + 2 * tg;
            if (c + 1 < Nd) {
                float cb0 = biasRow ? biasRow[c]     : 0.f;
                float cb1 = biasRow ? biasRow[c + 1] : 0.f;
                if (r0 < M) {
                    C[(size_t)r0 * Nd + c]     = acc[i][j][0] + cb0;
                    C[(size_t)r0 * Nd + c + 1] = acc[i][j][1] + cb1;
                }
                if (r0 + 8 < M) {
                    C[(size_t)(r0 + 8) * Nd + c]     = acc[i][j][2] + cb0;
                    C[(size_t)(r0 + 8) * Nd + c + 1] = acc[i][j][3] + cb1;
                }
            }
        }
    }
}

// Wrappers binding device-global scratch.
__global__ void k_dummy() {}

// ---------------------------------------------------------------------------
// Launch
// ---------------------------------------------------------------------------
extern "C" void kernel_launch(void* const* d_in, const int* in_sizes, int n_in,
                              void* d_out, int out_size)
{
    const float *x = 0, *text = 0, *W1 = 0, *b1 = 0, *W2 = 0, *b2 = 0, *Wc = 0, *bc = 0;
    const int   *ei = 0;
    int nbias = 0;
    for (int i = 0; i < n_in; i++) {
        int sz = in_sizes[i];
        if      (sz == NMAX * INCH)          x    = (const float*)d_in[i];
        else if (sz == 2 * EMAX)             ei   = (const int*)d_in[i];
        else if (sz == TEXTD)                text = (const float*)d_in[i];
        else if (sz == INCH * HID)           W1   = (const float*)d_in[i];
        else if (sz == HID * HID)            W2   = (const float*)d_in[i];
        else if (sz == (HID + TEXTD) * OUTC) Wc   = (const float*)d_in[i];
        else if (sz == OUTC)                 bc   = (const float*)d_in[i];
        else if (sz == HID) {
            if (nbias++ == 0) b1 = (const float*)d_in[i];
            else              b2 = (const float*)d_in[i];
        }
    }
    float* out = (float*)d_out;

    const int N = NMAX;
    const int E = EMAX;
    const int* src = ei;
    const int* dst = ei + E;

    const int T = 256;
    const int nseg = (N + SEG - 1) / SEG;

    // CSR build
    k_zero<<<(N + T - 1) / T, T>>>(N);
    k_count_deg<<<(E + T - 1) / T, T>>>(dst, E, N);
    k_finalize_deg<<<(N + T - 1) / T, T>>>(N);
    k_scan1<<<nseg, SEG>>>(N);
    k_scan2<<<1, 64>>>(nseg, N);
    k_scan3<<<nseg, SEG>>>(N);
    k_fill<<<(E + T - 1) / T, T>>>(src, dst, E, N);

    // constant classifier row
    k_crow<<<(OUTC + 31) / 32, T>>>(Wc, bc, text);

    const int aggBlocks = (N * 32 + T - 1) / T;
    dim3 gridH(1, (N + 127) / 128);                 // Nd=128 -> 1 col tile
    dim3 gridC((OUTC + 127) / 128, (N + 127) / 128);

    // Device pointers for scratch used as GEMM operands (device-linked symbols
    // resolve at compile time inside kernels; here we pass via the kernels'
    // own global references using small shim launches is unnecessary — the
    // generic GEMM takes raw pointers, and taking the address of __device__
    // globals in host code is invalid. Instead we obtain them via kernel
    // argument-free shims? Simpler: the GEMM reads A/B/C as parameters, so we
    // pass the globals through device-side address capture below.
    // NOTE: &g_h1 etc. in host code yields the device address under nvcc's
    // unified addressing for __device__ variables ONLY via cudaGetSymbolAddress,
    // which we avoid. Therefore use small constant wrappers:
    // (declared above as direct-global kernels in earlier rounds; here we use
    // device-pointer-capture kernels.)

    // layer 1: h1 = x @ W1
    {
        // capture device addresses once per launch via a tiny kernel is
        // overkill: __device__ arrays CAN be referenced in device code only.
        // We therefore launch GEMMs through wrapper kernels below.
    }
    extern __global__ void k_g1(const float*, const float*, int);
    // (fallthrough to wrapper launches)

    void dummy(); // unused

    // Wrapper launches (defined after this function? no — C++ requires
    // definitions; see wrappers below this comment in file order.)
    // -- actual launches happen via the wrappers defined above main launcher --
    // layer 1
    {
        extern void launch_gemm1(const float*, const float*, int, dim3, int);
    }
    // To keep this simple and correct, wrappers are defined as __global__
    // kernels below and declared here:
    {
        void* dummy2 = 0; (void)dummy2;
    }

    // real sequence:
    {
        extern __global__ void kw_gemm1(const float* x, const float* W1, int M);
        extern __global__ void kw_gemm2(const float* W2, int M);
        extern __global__ void kw_gemm3(const float* Wc, float* out, int M);
        kw_gemm1<<<gridH, T>>>(x, W1, N);
        k_agg1<<<aggBlocks, T>>>(b1, N);
        kw_gemm2<<<gridH, T>>>(W2, N);
        k_agg2<<<aggBlocks, T>>>(b2, N);
        kw_gemm3<<<gridC, T>>>(Wc, out, N);
    }
}

// ---------------------------------------------------------------------------
// GEMM wrappers: bind device-global scratch as operands, then call the
// generic tf32 body inline (same code path as k_gemm_tf32).
// ---------------------------------------------------------------------------
__device__ __forceinline__ void gemm_tf32_body(
    const float* __restrict__ A, int lda,
    const float* __restrict__ B,
    float* __restrict__ C,
    const float* __restrict__ biasRow,
    int M, int Nd, int K)
{
    __shared__ uint32_t As[128][20];
    __shared__ uint32_t Bs[16][136];

    const int tid  = threadIdx.x;
    const int lane = tid & 31;
    const int warp = tid >> 5;
    const int wm   = warp & 3;
    const int wn   = warp >> 2;
    const int bm   = blockIdx.y * 128;
    const int bn   = blockIdx.x * 128;
    const int g    = lane >> 2;
    const int tg   = lane & 3;

    float acc[2][8][4];
    #pragma unroll
    for (int i = 0; i < 2; i++)
        #pragma unroll
        for (int j = 0; j < 8; j++)
            #pragma unroll
            for (int r = 0; r < 4; r++) acc[i][j][r] = 0.0f;

    for (int k0 = 0; k0 < K; k0 += 16) {
        #pragma unroll
        for (int q = tid; q < 512; q += 256) {
            int row = q >> 2, quad = (q & 3) * 4;
            int gr = bm + row;
            float4 v = make_float4(0.f, 0.f, 0.f, 0.f);
            if (gr < M)
                v = *(const float4*)(A + (size_t)gr * lda + k0 + quad);
            As[row][quad + 0] = f2tf32(v.x);
            As[row][quad + 1] = f2tf32(v.y);
            As[row][quad + 2] = f2tf32(v.z);
            As[row][quad + 3] = f2tf32(v.w);
        }
        #pragma unroll
        for (int q = tid; q < 512; q += 256) {
            int row = q >> 5, c4 = (q & 31) * 4;
            int gc = bn + c4;
            float4 v = make_float4(0.f, 0.f, 0.f, 0.f);
            if (gc + 3 < Nd)
                v = *(const float4*)(B + (size_t)(k0 + row) * Nd + gc);
            Bs[row][c4 + 0] = f2tf32(v.x);
            Bs[row][c4 + 1] = f2tf32(v.y);
            Bs[row][c4 + 2] = f2tf32(v.z);
            Bs[row][c4 + 3] = f2tf32(v.w);
        }
        __syncthreads();

        #pragma unroll
        for (int ka = 0; ka < 16; ka += 8) {
            uint32_t a[2][4];
            #pragma unroll
            for (int i = 0; i < 2; i++) {
                int rb = wm * 32 + i * 16 + g;
                a[i][0] = As[rb][ka + tg];
                a[i][1] = As[rb + 8][ka + tg];
                a[i][2] = As[rb][ka + tg + 4];
                a[i][3] = As[rb + 8][ka + tg + 4];
            }
            #pragma unroll
            for (int j = 0; j < 8; j++) {
                int nb = wn * 64 + j * 8 + g;
                uint32_t b0 = Bs[ka + tg][nb];
                uint32_t b1 = Bs[ka + tg + 4][nb];
                #pragma unroll
                for (int i = 0; i < 2; i++) {
                    asm volatile(
                        "mma.sync.aligned.m16n8k8.row.col.f32.tf32.tf32.f32 "
                        "{%0,%1,%2,%3}, {%4,%5,%6,%7}, {%8,%9}, {%0,%1,%2,%3};"
                        : "+f"(acc[i][j][0]), "+f"(acc[i][j][1]),
                          "+f"(acc[i][j][2]), "+f"(acc[i][j][3])
                        : "r"(a[i][0]), "r"(a[i][1]), "r"(a[i][2]), "r"(a[i][3]),
                          "r"(b0), "r"(b1));
                }
            }
        }
        __syncthreads();
    }

    #pragma unroll
    for (int i = 0; i < 2; i++) {
        int r0 = bm + wm * 32 + i * 16 + g;
        #pragma unroll
        for (int j = 0; j < 8; j++) {
            int c = bn + wn * 64 + j * 8 + 2 * tg;
            if (c + 1 < Nd) {
                float cb0 = biasRow ? biasRow[c]     : 0.f;
                float cb1 = biasRow ? biasRow[c + 1] : 0.f;
                if (r0 < M) {
                    C[(size_t)r0 * Nd + c]     = acc[i][j][0] + cb0;
                    C[(size_t)r0 * Nd + c + 1] = acc[i][j][1] + cb1;
                }
                if (r0 + 8 < M) {
                    C[(size_t)(r0 + 8) * Nd + c]     = acc[i][j][2] + cb0;
                    C[(size_t)(r0 + 8) * Nd + c + 1] = acc[i][j][3] + cb1;
                }
            }
        }
    }
}

__global__ __launch_bounds__(256) void kw_gemm1(const float* __restrict__ x,
                                                const float* __restrict__ W1, int M) {
    gemm_tf32_body(x, INCH, W1, g_h1, nullptr, M, HID, INCH);
}
__global__ __launch_bounds__(256) void kw_gemm2(const float* __restrict__ W2, int M) {
    gemm_tf32_body(g_agg1, HID, W2, g_h2, nullptr, M, HID, HID);
}
__global__ __launch_bounds__(256) void kw_gemm3(const float* __restrict__ Wc,
                                                float* __restrict__ out, int M) {
    gemm_tf32_body(g_agg2, HID, Wc, out, g_crow, M, OUTC, HID);
}